// round 1
// baseline (speedup 1.0000x reference)
#include <cuda_runtime.h>
#include <mma.h>
#include <math.h>

using namespace nvcuda;

// Problem constants
#define T_TOK 2048   // S*B tokens
#define H_DIM 1024
#define F_DIM 4096
#define E_NUM 4
#define CAP   2048   // per-expert slot capacity (worst case: every token)

// GEMM tiling
#define BM 64
#define BN 64
#define BK 32
#define LDA 36       // BK + 4 pad (multiple of 4 floats for wmma)
#define LDB 68       // BN + 4 pad
#define LDC 68

// ---------------- scratch (static device globals; no allocation) ------------
__device__ float g_act[(size_t)E_NUM * CAP * F_DIM];   // fc1+gelu activations
__device__ float g_y[(size_t)E_NUM * CAP * H_DIM];     // fc2 outputs per slot
__device__ int   g_cnt[E_NUM];
__device__ int   g_tok[E_NUM * CAP];                   // slot -> token
__device__ int   g_slot[T_TOK * E_NUM];                // (token,e) -> global slot

// ---------------- routing compaction ----------------------------------------
__global__ void zero_cnt_kernel() {
    if (threadIdx.x < E_NUM) g_cnt[threadIdx.x] = 0;
}

__global__ void route_kernel(const float* __restrict__ probs) {
    int t = blockIdx.x * blockDim.x + threadIdx.x;
    if (t >= T_TOK) return;
#pragma unroll
    for (int e = 0; e < E_NUM; e++) {
        float p = probs[t * E_NUM + e];
        if (p > 0.0f) {
            int pos = atomicAdd(&g_cnt[e], 1);
            g_tok[e * CAP + pos] = t;
            g_slot[t * E_NUM + e] = e * CAP + pos;
        }
    }
}

// ---------------- GEMM1: act = gelu( gather(X) @ w1[e] ) --------------------
// grid: (F/BN, CAP/BM, E), block: 128 threads (4 warps, each 32x32 of C)
__global__ __launch_bounds__(128) void gemm1_kernel(
    const float* __restrict__ X, const float* __restrict__ W1)
{
    __shared__ __align__(16) float smem[BM * LDA + BK * LDB];
    float* sA = smem;                 // [BM][LDA]
    float* sB = smem + BM * LDA;      // [BK][LDB]

    const int e   = blockIdx.z;
    const int cnt = g_cnt[e];
    const int m0  = blockIdx.y * BM;
    if (m0 >= cnt) return;
    const int n0  = blockIdx.x * BN;
    const int tid = threadIdx.x;
    const int w   = tid >> 5;
    const int wr  = w >> 1;           // warp row (0..1), 32 rows each
    const int wc  = w & 1;            // warp col (0..1), 32 cols each

    wmma::fragment<wmma::accumulator, 16, 16, 8, float> acc[2][2];
#pragma unroll
    for (int i = 0; i < 2; i++)
#pragma unroll
        for (int j = 0; j < 2; j++) wmma::fill_fragment(acc[i][j], 0.0f);

    for (int k0 = 0; k0 < H_DIM; k0 += BK) {
        // load A tile (gathered token rows), 64x32, 4 float4 per thread
#pragma unroll
        for (int i = 0; i < 4; i++) {
            int lin = tid + i * 128;
            int row = lin >> 3;            // / (BK/4=8)
            int c4  = (lin & 7) * 4;
            float4 v = make_float4(0.f, 0.f, 0.f, 0.f);
            int m = m0 + row;
            if (m < cnt) {
                int tok = g_tok[e * CAP + m];
                v = *reinterpret_cast<const float4*>(
                        &X[(size_t)tok * H_DIM + k0 + c4]);
            }
            *reinterpret_cast<float4*>(&sA[row * LDA + c4]) = v;
        }
        // load B tile (w1[e]), 32x64, 4 float4 per thread
#pragma unroll
        for (int i = 0; i < 4; i++) {
            int lin = tid + i * 128;
            int row = lin >> 4;            // / (BN/4=16)
            int c4  = (lin & 15) * 4;
            float4 v = *reinterpret_cast<const float4*>(
                &W1[((size_t)e * H_DIM + k0 + row) * F_DIM + n0 + c4]);
            *reinterpret_cast<float4*>(&sB[row * LDB + c4]) = v;
        }
        __syncthreads();

#pragma unroll
        for (int kk = 0; kk < BK; kk += 8) {
            wmma::fragment<wmma::matrix_a, 16, 16, 8, wmma::precision::tf32,
                           wmma::row_major> a[2];
            wmma::fragment<wmma::matrix_b, 16, 16, 8, wmma::precision::tf32,
                           wmma::row_major> b[2];
#pragma unroll
            for (int i = 0; i < 2; i++) {
                wmma::load_matrix_sync(a[i], &sA[(wr * 32 + i * 16) * LDA + kk], LDA);
#pragma unroll
                for (int t = 0; t < a[i].num_elements; t++)
                    a[i].x[t] = wmma::__float_to_tf32(a[i].x[t]);
            }
#pragma unroll
            for (int j = 0; j < 2; j++) {
                wmma::load_matrix_sync(b[j], &sB[kk * LDB + wc * 32 + j * 16], LDB);
#pragma unroll
                for (int t = 0; t < b[j].num_elements; t++)
                    b[j].x[t] = wmma::__float_to_tf32(b[j].x[t]);
            }
#pragma unroll
            for (int i = 0; i < 2; i++)
#pragma unroll
                for (int j = 0; j < 2; j++)
                    wmma::mma_sync(acc[i][j], a[i], b[j], acc[i][j]);
        }
        __syncthreads();
    }

    // epilogue: stage C in smem (alias), apply exact gelu, store to g_act
    float* sC = smem;
#pragma unroll
    for (int i = 0; i < 2; i++)
#pragma unroll
        for (int j = 0; j < 2; j++)
            wmma::store_matrix_sync(&sC[(wr * 32 + i * 16) * LDC + wc * 32 + j * 16],
                                    acc[i][j], LDC, wmma::mem_row_major);
    __syncthreads();
#pragma unroll
    for (int i = 0; i < 32; i++) {          // 64*64 / 128 threads
        int lin = tid + i * 128;
        int row = lin >> 6;
        int col = lin & 63;
        int m = m0 + row;
        if (m < cnt) {
            float v = sC[row * LDC + col];
            v = 0.5f * v * (1.0f + erff(v * 0.70710678118654752f));
            g_act[(size_t)(e * CAP + m) * F_DIM + n0 + col] = v;
        }
    }
}

// ---------------- GEMM2: y = act @ w2[e] ------------------------------------
// grid: (H/BN, CAP/BM, E), block: 128 threads
__global__ __launch_bounds__(128) void gemm2_kernel(const float* __restrict__ W2)
{
    __shared__ __align__(16) float smem[BM * LDA + BK * LDB];
    float* sA = smem;
    float* sB = smem + BM * LDA;

    const int e   = blockIdx.z;
    const int cnt = g_cnt[e];
    const int m0  = blockIdx.y * BM;
    if (m0 >= cnt) return;
    const int n0  = blockIdx.x * BN;
    const int tid = threadIdx.x;
    const int w   = tid >> 5;
    const int wr  = w >> 1;
    const int wc  = w & 1;

    wmma::fragment<wmma::accumulator, 16, 16, 8, float> acc[2][2];
#pragma unroll
    for (int i = 0; i < 2; i++)
#pragma unroll
        for (int j = 0; j < 2; j++) wmma::fill_fragment(acc[i][j], 0.0f);

    const float* A = &g_act[(size_t)(e * CAP) * F_DIM];

    for (int k0 = 0; k0 < F_DIM; k0 += BK) {
#pragma unroll
        for (int i = 0; i < 4; i++) {
            int lin = tid + i * 128;
            int row = lin >> 3;
            int c4  = (lin & 7) * 4;
            // rows >= cnt hold stale data; their products only reach y rows
            // that are never read by combine (rows are independent in GEMM)
            float4 v = *reinterpret_cast<const float4*>(
                &A[(size_t)(m0 + row) * F_DIM + k0 + c4]);
            *reinterpret_cast<float4*>(&sA[row * LDA + c4]) = v;
        }
#pragma unroll
        for (int i = 0; i < 4; i++) {
            int lin = tid + i * 128;
            int row = lin >> 4;
            int c4  = (lin & 15) * 4;
            float4 v = *reinterpret_cast<const float4*>(
                &W2[((size_t)e * F_DIM + k0 + row) * H_DIM + n0 + c4]);
            *reinterpret_cast<float4*>(&sB[row * LDB + c4]) = v;
        }
        __syncthreads();

#pragma unroll
        for (int kk = 0; kk < BK; kk += 8) {
            wmma::fragment<wmma::matrix_a, 16, 16, 8, wmma::precision::tf32,
                           wmma::row_major> a[2];
            wmma::fragment<wmma::matrix_b, 16, 16, 8, wmma::precision::tf32,
                           wmma::row_major> b[2];
#pragma unroll
            for (int i = 0; i < 2; i++) {
                wmma::load_matrix_sync(a[i], &sA[(wr * 32 + i * 16) * LDA + kk], LDA);
#pragma unroll
                for (int t = 0; t < a[i].num_elements; t++)
                    a[i].x[t] = wmma::__float_to_tf32(a[i].x[t]);
            }
#pragma unroll
            for (int j = 0; j < 2; j++) {
                wmma::load_matrix_sync(b[j], &sB[kk * LDB + wc * 32 + j * 16], LDB);
#pragma unroll
                for (int t = 0; t < b[j].num_elements; t++)
                    b[j].x[t] = wmma::__float_to_tf32(b[j].x[t]);
            }
#pragma unroll
            for (int i = 0; i < 2; i++)
#pragma unroll
                for (int j = 0; j < 2; j++)
                    wmma::mma_sync(acc[i][j], a[i], b[j], acc[i][j]);
        }
        __syncthreads();
    }

    // epilogue: store accumulators straight to g_y (padded rows harmless)
#pragma unroll
    for (int i = 0; i < 2; i++)
#pragma unroll
        for (int j = 0; j < 2; j++)
            wmma::store_matrix_sync(
                &g_y[(size_t)(e * CAP + m0 + wr * 32 + i * 16) * H_DIM
                     + n0 + wc * 32 + j * 16],
                acc[i][j], H_DIM, wmma::mem_row_major);
}

// ---------------- combine: out = residual + sum_e p * y ---------------------
__global__ void combine_kernel(const float* __restrict__ res,
                               const float* __restrict__ probs,
                               float* __restrict__ out)
{
    int t = blockIdx.x;
    int h = threadIdx.x * 4;
    float4 acc = *reinterpret_cast<const float4*>(&res[(size_t)t * H_DIM + h]);
#pragma unroll
    for (int e = 0; e < E_NUM; e++) {
        float p = probs[t * E_NUM + e];
        if (p > 0.0f) {
            int s = g_slot[t * E_NUM + e];
            float4 y = *reinterpret_cast<const float4*>(
                &g_y[(size_t)s * H_DIM + h]);
            acc.x += p * y.x;
            acc.y += p * y.y;
            acc.z += p * y.z;
            acc.w += p * y.w;
        }
    }
    *reinterpret_cast<float4*>(&out[(size_t)t * H_DIM + h]) = acc;
}

// ---------------- launcher ---------------------------------------------------
extern "C" void kernel_launch(void* const* d_in, const int* in_sizes, int n_in,
                              void* d_out, int out_size)
{
    const float* x     = (const float*)d_in[0];  // hidden_states [T, H]
    const float* res   = (const float*)d_in[1];  // mlp_residual  [T, H]
    const float* probs = (const float*)d_in[2];  // probs         [T, E] (zero off-route)
    // d_in[3] routing_map unused: probs > 0 iff routed
    const float* w1    = (const float*)d_in[4];  // [E, H, F]
    const float* w2    = (const float*)d_in[5];  // [E, F, H]
    float* out = (float*)d_out;

    zero_cnt_kernel<<<1, 32>>>();
    route_kernel<<<T_TOK / 256, 256>>>(probs);
    gemm1_kernel<<<dim3(F_DIM / BN, CAP / BM, E_NUM), 128>>>(x, w1);
    gemm2_kernel<<<dim3(H_DIM / BN, CAP / BM, E_NUM), 128>>>(w2);
    combine_kernel<<<T_TOK, 256>>>(res, probs, out);
}

// round 4
// speedup vs baseline: 1.2285x; 1.2285x over previous
#include <cuda_runtime.h>
#include <mma.h>
#include <math.h>
#include <stdint.h>

using namespace nvcuda;

// Problem constants
#define T_TOK 2048
#define H_DIM 1024
#define F_DIM 4096
#define E_NUM 4
#define CAP   2048

// GEMM tiling: 128x128 block tile, BK=32, 2-stage cp.async pipeline
#define BM 128
#define BN 128
#define BK 32
#define LDA 36       // BK + 4 pad
#define LDB 132      // BN + 4 pad
#define LDC 132
#define NTHREADS 256

#define STAGE_FLOATS (BM * LDA + BK * LDB)                   // 8832
#define SMEM_BYTES   (2 * STAGE_FLOATS * (int)sizeof(float)) // 70656

// ---------------- scratch (static device globals; no allocation) ------------
__device__ float g_act[(size_t)E_NUM * CAP * F_DIM];
__device__ float g_y[(size_t)E_NUM * CAP * H_DIM];
__device__ int   g_cnt[E_NUM];
__device__ int   g_tok[E_NUM * CAP];
__device__ int   g_slot[T_TOK * E_NUM];

// ---------------- cp.async helpers ------------------------------------------
__device__ __forceinline__ void cp_async16(float* smem_dst, const float* gmem_src,
                                           bool pred) {
    unsigned int saddr = (unsigned int)__cvta_generic_to_shared(smem_dst);
    int sz = pred ? 16 : 0;   // src-size 0 -> zero-fill destination
    asm volatile("cp.async.cg.shared.global [%0], [%1], 16, %2;\n"
                 :: "r"(saddr), "l"(gmem_src), "r"(sz));
}
#define CP_COMMIT()  asm volatile("cp.async.commit_group;\n" ::)
#define CP_WAIT(n)   asm volatile("cp.async.wait_group %0;\n" :: "n"(n))

// ---------------- routing compaction ----------------------------------------
__global__ void zero_cnt_kernel() {
    if (threadIdx.x < E_NUM) g_cnt[threadIdx.x] = 0;
}

__global__ void route_kernel(const float* __restrict__ probs) {
    int t = blockIdx.x * blockDim.x + threadIdx.x;
    if (t >= T_TOK) return;
#pragma unroll
    for (int e = 0; e < E_NUM; e++) {
        float p = probs[t * E_NUM + e];
        if (p > 0.0f) {
            int pos = atomicAdd(&g_cnt[e], 1);
            g_tok[e * CAP + pos] = t;
            g_slot[t * E_NUM + e] = e * CAP + pos;
        }
    }
}

// ---------------- shared MMA core -------------------------------------------
// 8 warps: warp_m = w>>1 (4 rows of 32), warp_n = w&1 (2 cols of 64)
struct Frags {
    wmma::fragment<wmma::accumulator, 16, 16, 8, float> acc[2][4];
};

__device__ __forceinline__ void mma_stage(const float* sA, const float* sB,
                                          int warp_m, int warp_n, Frags& fr) {
#pragma unroll
    for (int kk = 0; kk < BK; kk += 8) {
        wmma::fragment<wmma::matrix_a, 16, 16, 8, wmma::precision::tf32,
                       wmma::row_major> a[2];
        wmma::fragment<wmma::matrix_b, 16, 16, 8, wmma::precision::tf32,
                       wmma::row_major> b[4];
#pragma unroll
        for (int i = 0; i < 2; i++) {
            wmma::load_matrix_sync(a[i], &sA[(warp_m * 32 + i * 16) * LDA + kk], LDA);
#pragma unroll
            for (int t = 0; t < a[i].num_elements; t++)
                a[i].x[t] = wmma::__float_to_tf32(a[i].x[t]);
        }
#pragma unroll
        for (int j = 0; j < 4; j++) {
            wmma::load_matrix_sync(b[j], &sB[kk * LDB + warp_n * 64 + j * 16], LDB);
#pragma unroll
            for (int t = 0; t < b[j].num_elements; t++)
                b[j].x[t] = wmma::__float_to_tf32(b[j].x[t]);
        }
#pragma unroll
        for (int i = 0; i < 2; i++)
#pragma unroll
            for (int j = 0; j < 4; j++)
                wmma::mma_sync(fr.acc[i][j], a[i], b[j], fr.acc[i][j]);
    }
}

// ---------------- GEMM1: act = gelu( gather(X) @ w1[e] ) --------------------
// grid: (F/BN=32, CAP/BM up to 16, E), block: 256
__global__ __launch_bounds__(NTHREADS, 2) void gemm1_kernel(
    const float* __restrict__ X, const float* __restrict__ W1)
{
    extern __shared__ __align__(16) float smem[];
    const int e   = blockIdx.z;
    const int cnt = g_cnt[e];
    const int m0  = blockIdx.y * BM;
    if (m0 >= cnt) return;
    const int n0  = blockIdx.x * BN;
    const int tid = threadIdx.x;
    const int w   = tid >> 5;
    const int warp_m = w >> 1;
    const int warp_n = w & 1;

    // A-tile loader: 128x32 floats = 1024 16B chunks, 4/thread (fixed rows)
    int a_row[4], a_col[4], a_tok[4];
    bool a_ok[4];
#pragma unroll
    for (int i = 0; i < 4; i++) {
        int id = tid + i * NTHREADS;
        a_row[i] = id >> 3;
        a_col[i] = (id & 7) * 4;
        int m = m0 + a_row[i];
        a_ok[i] = (m < cnt);
        a_tok[i] = a_ok[i] ? __ldg(&g_tok[e * CAP + m]) : 0;
    }
    // B-tile loader: 32x128 floats = 1024 chunks, 4/thread
    int b_row[4], b_col[4];
#pragma unroll
    for (int i = 0; i < 4; i++) {
        int id = tid + i * NTHREADS;
        b_row[i] = id >> 5;
        b_col[i] = (id & 31) * 4;
    }

    const float* W1e = &W1[(size_t)e * H_DIM * F_DIM];

    Frags fr;
#pragma unroll
    for (int i = 0; i < 2; i++)
#pragma unroll
        for (int j = 0; j < 4; j++) wmma::fill_fragment(fr.acc[i][j], 0.0f);

    const int NK = H_DIM / BK;   // 32

    {   // prefetch stage 0
        float* sA = smem;
        float* sB = smem + BM * LDA;
#pragma unroll
        for (int i = 0; i < 4; i++)
            cp_async16(&sA[a_row[i] * LDA + a_col[i]],
                       &X[(size_t)a_tok[i] * H_DIM + a_col[i]], a_ok[i]);
#pragma unroll
        for (int i = 0; i < 4; i++)
            cp_async16(&sB[b_row[i] * LDB + b_col[i]],
                       &W1e[(size_t)b_row[i] * F_DIM + n0 + b_col[i]], true);
        CP_COMMIT();
    }

    for (int kt = 0; kt < NK; kt++) {
        const int cur = kt & 1;
        if (kt + 1 < NK) {
            const int k0 = (kt + 1) * BK;
            float* sA = smem + (cur ^ 1) * STAGE_FLOATS;
            float* sB = sA + BM * LDA;
#pragma unroll
            for (int i = 0; i < 4; i++)
                cp_async16(&sA[a_row[i] * LDA + a_col[i]],
                           &X[(size_t)a_tok[i] * H_DIM + k0 + a_col[i]], a_ok[i]);
#pragma unroll
            for (int i = 0; i < 4; i++)
                cp_async16(&sB[b_row[i] * LDB + b_col[i]],
                           &W1e[(size_t)(k0 + b_row[i]) * F_DIM + n0 + b_col[i]], true);
            CP_COMMIT();
            CP_WAIT(1);
        } else {
            CP_WAIT(0);
        }
        __syncthreads();
        mma_stage(smem + cur * STAGE_FLOATS, smem + cur * STAGE_FLOATS + BM * LDA,
                  warp_m, warp_n, fr);
        __syncthreads();
    }

    // epilogue: stage C in smem, gelu, vectorized store
    float* sC = smem;
#pragma unroll
    for (int i = 0; i < 2; i++)
#pragma unroll
        for (int j = 0; j < 4; j++)
            wmma::store_matrix_sync(
                &sC[(warp_m * 32 + i * 16) * LDC + warp_n * 64 + j * 16],
                fr.acc[i][j], LDC, wmma::mem_row_major);
    __syncthreads();
#pragma unroll
    for (int i = 0; i < 16; i++) {
        int id  = tid + i * NTHREADS;
        int row = id >> 5;
        int c   = (id & 31) * 4;
        int m   = m0 + row;
        if (m < cnt) {
            float4 v = *reinterpret_cast<const float4*>(&sC[row * LDC + c]);
            v.x = 0.5f * v.x * (1.0f + erff(v.x * 0.70710678118654752f));
            v.y = 0.5f * v.y * (1.0f + erff(v.y * 0.70710678118654752f));
            v.z = 0.5f * v.z * (1.0f + erff(v.z * 0.70710678118654752f));
            v.w = 0.5f * v.w * (1.0f + erff(v.w * 0.70710678118654752f));
            *reinterpret_cast<float4*>(
                &g_act[(size_t)(e * CAP + m) * F_DIM + n0 + c]) = v;
        }
    }
}

// ---------------- GEMM2: y = act @ w2[e] ------------------------------------
// grid: (H/BN=8, CAP/BM up to 16, E), block: 256
__global__ __launch_bounds__(NTHREADS, 2) void gemm2_kernel(
    const float* __restrict__ W2)
{
    extern __shared__ __align__(16) float smem[];
    const int e   = blockIdx.z;
    const int cnt = g_cnt[e];
    const int m0  = blockIdx.y * BM;
    if (m0 >= cnt) return;
    const int n0  = blockIdx.x * BN;
    const int tid = threadIdx.x;
    const int w   = tid >> 5;
    const int warp_m = w >> 1;
    const int warp_n = w & 1;

    int a_row[4], a_col[4], b_row[4], b_col[4];
#pragma unroll
    for (int i = 0; i < 4; i++) {
        int id = tid + i * NTHREADS;
        a_row[i] = id >> 3;
        a_col[i] = (id & 7) * 4;
        b_row[i] = id >> 5;
        b_col[i] = (id & 31) * 4;
    }

    const float* A   = &g_act[(size_t)(e * CAP) * F_DIM];
    const float* W2e = &W2[(size_t)e * F_DIM * H_DIM];

    Frags fr;
#pragma unroll
    for (int i = 0; i < 2; i++)
#pragma unroll
        for (int j = 0; j < 4; j++) wmma::fill_fragment(fr.acc[i][j], 0.0f);

    const int NK = F_DIM / BK;   // 128

    {
        float* sA = smem;
        float* sB = smem + BM * LDA;
#pragma unroll
        for (int i = 0; i < 4; i++)
            cp_async16(&sA[a_row[i] * LDA + a_col[i]],
                       &A[(size_t)(m0 + a_row[i]) * F_DIM + a_col[i]], true);
#pragma unroll
        for (int i = 0; i < 4; i++)
            cp_async16(&sB[b_row[i] * LDB + b_col[i]],
                       &W2e[(size_t)b_row[i] * H_DIM + n0 + b_col[i]], true);
        CP_COMMIT();
    }

    for (int kt = 0; kt < NK; kt++) {
        const int cur = kt & 1;
        if (kt + 1 < NK) {
            const int k0 = (kt + 1) * BK;
            float* sA = smem + (cur ^ 1) * STAGE_FLOATS;
            float* sB = sA + BM * LDA;
#pragma unroll
            for (int i = 0; i < 4; i++)
                cp_async16(&sA[a_row[i] * LDA + a_col[i]],
                           &A[(size_t)(m0 + a_row[i]) * F_DIM + k0 + a_col[i]], true);
#pragma unroll
            for (int i = 0; i < 4; i++)
                cp_async16(&sB[b_row[i] * LDB + b_col[i]],
                           &W2e[(size_t)(k0 + b_row[i]) * H_DIM + n0 + b_col[i]], true);
            CP_COMMIT();
            CP_WAIT(1);
        } else {
            CP_WAIT(0);
        }
        __syncthreads();
        mma_stage(smem + cur * STAGE_FLOATS, smem + cur * STAGE_FLOATS + BM * LDA,
                  warp_m, warp_n, fr);
        __syncthreads();
    }

#pragma unroll
    for (int i = 0; i < 2; i++)
#pragma unroll
        for (int j = 0; j < 4; j++)
            wmma::store_matrix_sync(
                &g_y[(size_t)(e * CAP + m0 + warp_m * 32 + i * 16) * H_DIM
                     + n0 + warp_n * 64 + j * 16],
                fr.acc[i][j], H_DIM, wmma::mem_row_major);
}

// ---------------- combine: out = residual + sum_e p * y ---------------------
__global__ void combine_kernel(const float* __restrict__ res,
                               const float* __restrict__ probs,
                               float* __restrict__ out)
{
    int t = blockIdx.x;
    int h = threadIdx.x * 4;
    float4 acc = *reinterpret_cast<const float4*>(&res[(size_t)t * H_DIM + h]);
#pragma unroll
    for (int e = 0; e < E_NUM; e++) {
        float p = probs[t * E_NUM + e];
        if (p > 0.0f) {
            int s = g_slot[t * E_NUM + e];
            float4 y = *reinterpret_cast<const float4*>(&g_y[(size_t)s * H_DIM + h]);
            acc.x += p * y.x;
            acc.y += p * y.y;
            acc.z += p * y.z;
            acc.w += p * y.w;
        }
    }
    *reinterpret_cast<float4*>(&out[(size_t)t * H_DIM + h]) = acc;
}

// ---------------- launcher ---------------------------------------------------
extern "C" void kernel_launch(void* const* d_in, const int* in_sizes, int n_in,
                              void* d_out, int out_size)
{
    const float* x     = (const float*)d_in[0];
    const float* res   = (const float*)d_in[1];
    const float* probs = (const float*)d_in[2];
    const float* w1    = (const float*)d_in[4];
    const float* w2    = (const float*)d_in[5];
    float* out = (float*)d_out;

    (void)cudaFuncSetAttribute(gemm1_kernel,
                               cudaFuncAttributeMaxDynamicSharedMemorySize, SMEM_BYTES);
    (void)cudaFuncSetAttribute(gemm2_kernel,
                               cudaFuncAttributeMaxDynamicSharedMemorySize, SMEM_BYTES);

    zero_cnt_kernel<<<1, 32>>>();
    route_kernel<<<T_TOK / 256, 256>>>(probs);
    gemm1_kernel<<<dim3(F_DIM / BN, CAP / BM, E_NUM), NTHREADS, SMEM_BYTES>>>(x, w1);
    gemm2_kernel<<<dim3(H_DIM / BN, CAP / BM, E_NUM), NTHREADS, SMEM_BYTES>>>(w2);
    combine_kernel<<<T_TOK, 256>>>(res, probs, out);
}

// round 7
// speedup vs baseline: 4.3027x; 3.5024x over previous
#include <cuda_runtime.h>
#include <cuda_fp16.h>
#include <mma.h>
#include <math.h>
#include <stdint.h>

using namespace nvcuda;

// Problem constants
#define T_TOK 2048
#define H_DIM 1024
#define F_DIM 4096
#define E_NUM 4
#define CAP   2048

// GEMM tiling: 128x128 tile, BK=64 halves, 2-stage cp.async pipeline
#define BM 128
#define BN 128
#define BKH 64          // K elements (half) per stage
#define LDA 72          // BKH + 8 pad (halves)
#define LDB 136         // BN + 8 pad (halves)
#define LDC 132         // floats, epilogue staging
#define NTHREADS 256

#define STAGE_HALFS (BM * LDA + BKH * LDB)                 // 17920
#define SMEM_BYTES  (2 * STAGE_HALFS * (int)sizeof(__half)) // 71680 (>= 128*132*4 epilogue)

// ---------------- scratch (static device globals; no allocation) ------------
__device__ __half g_xh[(size_t)T_TOK * H_DIM];
__device__ __half g_w1h[(size_t)E_NUM * H_DIM * F_DIM];
__device__ __half g_w2h[(size_t)E_NUM * F_DIM * H_DIM];
__device__ __half g_act[(size_t)E_NUM * CAP * F_DIM];
__device__ float  g_y[(size_t)E_NUM * CAP * H_DIM];
__device__ int    g_cnt[E_NUM];
__device__ int    g_tok[E_NUM * CAP];
__device__ int    g_slot[T_TOK * E_NUM];

// ---------------- cp.async helpers ------------------------------------------
__device__ __forceinline__ void cp_async16(__half* smem_dst, const __half* gmem_src,
                                           bool pred) {
    unsigned int saddr = (unsigned int)__cvta_generic_to_shared(smem_dst);
    int sz = pred ? 16 : 0;   // src-size 0 -> zero-fill destination
    asm volatile("cp.async.cg.shared.global [%0], [%1], 16, %2;\n"
                 :: "r"(saddr), "l"(gmem_src), "r"(sz));
}
#define CP_COMMIT()  asm volatile("cp.async.commit_group;\n" ::)
#define CP_WAIT(n)   asm volatile("cp.async.wait_group %0;\n" :: "n"(n))

// ---------------- fp32 -> fp16 convert ---------------------------------------
__global__ void f2h_kernel(const float* __restrict__ src, __half* __restrict__ dst,
                           size_t n4) {   // n4 = n/4
    size_t i = (size_t)blockIdx.x * blockDim.x + threadIdx.x;
    size_t stride = (size_t)gridDim.x * blockDim.x;
    for (; i < n4; i += stride) {
        float4 v = reinterpret_cast<const float4*>(src)[i];
        __half2 h0 = __floats2half2_rn(v.x, v.y);
        __half2 h1 = __floats2half2_rn(v.z, v.w);
        reinterpret_cast<__half2*>(dst)[i * 2 + 0] = h0;
        reinterpret_cast<__half2*>(dst)[i * 2 + 1] = h1;
    }
}

// ---------------- routing compaction ----------------------------------------
__global__ void zero_cnt_kernel() {
    if (threadIdx.x < E_NUM) g_cnt[threadIdx.x] = 0;
}

__global__ void route_kernel(const float* __restrict__ probs) {
    int t = blockIdx.x * blockDim.x + threadIdx.x;
    if (t >= T_TOK) return;
#pragma unroll
    for (int e = 0; e < E_NUM; e++) {
        float p = probs[t * E_NUM + e];
        if (p > 0.0f) {
            int pos = atomicAdd(&g_cnt[e], 1);
            g_tok[e * CAP + pos] = t;
            g_slot[t * E_NUM + e] = e * CAP + pos;
        }
    }
}

// ---------------- shared MMA core -------------------------------------------
// 8 warps: warp_m = w>>1 (4 rows of 32), warp_n = w&1 (2 cols of 64)
struct Frags {
    wmma::fragment<wmma::accumulator, 16, 16, 16, float> acc[2][4];
};

__device__ __forceinline__ void mma_stage(const __half* sA, const __half* sB,
                                          int warp_m, int warp_n, Frags& fr) {
#pragma unroll
    for (int kk = 0; kk < BKH; kk += 16) {
        wmma::fragment<wmma::matrix_a, 16, 16, 16, __half, wmma::row_major> a[2];
        wmma::fragment<wmma::matrix_b, 16, 16, 16, __half, wmma::row_major> b[4];
#pragma unroll
        for (int i = 0; i < 2; i++)
            wmma::load_matrix_sync(a[i], &sA[(warp_m * 32 + i * 16) * LDA + kk], LDA);
#pragma unroll
        for (int j = 0; j < 4; j++)
            wmma::load_matrix_sync(b[j], &sB[kk * LDB + warp_n * 64 + j * 16], LDB);
#pragma unroll
        for (int i = 0; i < 2; i++)
#pragma unroll
            for (int j = 0; j < 4; j++)
                wmma::mma_sync(fr.acc[i][j], a[i], b[j], fr.acc[i][j]);
    }
}

// ---------------- GEMM1: act = gelu( gather(Xh) @ w1h ) ---------------------
// grid: (F/BN=32, CAP/BM=16, E), block: 256
__global__ __launch_bounds__(NTHREADS, 2) void gemm1_kernel()
{
    extern __shared__ __align__(16) __half smem[];
    const int e   = blockIdx.z;
    const int cnt = g_cnt[e];
    const int m0  = blockIdx.y * BM;
    if (m0 >= cnt) return;
    const int n0  = blockIdx.x * BN;
    const int tid = threadIdx.x;
    const int w   = tid >> 5;
    const int warp_m = w >> 1;
    const int warp_n = w & 1;

    // A tile: 128 rows x 64 halves = 8 chunks(16B)/row, 1024 chunks, 4/thread
    int a_row[4], a_col[4], a_tok[4];
    bool a_ok[4];
#pragma unroll
    for (int i = 0; i < 4; i++) {
        int id = tid + i * NTHREADS;
        a_row[i] = id >> 3;
        a_col[i] = (id & 7) * 8;          // half offset
        int m = m0 + a_row[i];
        a_ok[i] = (m < cnt);
        a_tok[i] = a_ok[i] ? __ldg(&g_tok[e * CAP + m]) : 0;
    }
    // B tile: 64 rows x 128 halves = 16 chunks/row, 1024 chunks, 4/thread
    int b_row[4], b_col[4];
#pragma unroll
    for (int i = 0; i < 4; i++) {
        int id = tid + i * NTHREADS;
        b_row[i] = id >> 4;
        b_col[i] = (id & 15) * 8;
    }

    const __half* W1e = &g_w1h[(size_t)e * H_DIM * F_DIM];

    Frags fr;
#pragma unroll
    for (int i = 0; i < 2; i++)
#pragma unroll
        for (int j = 0; j < 4; j++) wmma::fill_fragment(fr.acc[i][j], 0.0f);

    const int NK = H_DIM / BKH;   // 16

    {   // prefetch stage 0
        __half* sA = smem;
        __half* sB = smem + BM * LDA;
#pragma unroll
        for (int i = 0; i < 4; i++)
            cp_async16(&sA[a_row[i] * LDA + a_col[i]],
                       &g_xh[(size_t)a_tok[i] * H_DIM + a_col[i]], a_ok[i]);
#pragma unroll
        for (int i = 0; i < 4; i++)
            cp_async16(&sB[b_row[i] * LDB + b_col[i]],
                       &W1e[(size_t)b_row[i] * F_DIM + n0 + b_col[i]], true);
        CP_COMMIT();
    }

    for (int kt = 0; kt < NK; kt++) {
        const int cur = kt & 1;
        if (kt + 1 < NK) {
            const int k0 = (kt + 1) * BKH;
            __half* sA = smem + (cur ^ 1) * STAGE_HALFS;
            __half* sB = sA + BM * LDA;
#pragma unroll
            for (int i = 0; i < 4; i++)
                cp_async16(&sA[a_row[i] * LDA + a_col[i]],
                           &g_xh[(size_t)a_tok[i] * H_DIM + k0 + a_col[i]], a_ok[i]);
#pragma unroll
            for (int i = 0; i < 4; i++)
                cp_async16(&sB[b_row[i] * LDB + b_col[i]],
                           &W1e[(size_t)(k0 + b_row[i]) * F_DIM + n0 + b_col[i]], true);
            CP_COMMIT();
            CP_WAIT(1);
        } else {
            CP_WAIT(0);
        }
        __syncthreads();
        mma_stage(smem + cur * STAGE_HALFS, smem + cur * STAGE_HALFS + BM * LDA,
                  warp_m, warp_n, fr);
        __syncthreads();
    }

    // epilogue: stage C (float) in smem, gelu, convert to half, store
    float* sC = reinterpret_cast<float*>(smem);
#pragma unroll
    for (int i = 0; i < 2; i++)
#pragma unroll
        for (int j = 0; j < 4; j++)
            wmma::store_matrix_sync(
                &sC[(warp_m * 32 + i * 16) * LDC + warp_n * 64 + j * 16],
                fr.acc[i][j], LDC, wmma::mem_row_major);
    __syncthreads();
#pragma unroll
    for (int i = 0; i < 16; i++) {       // 4096 4-elem groups / 256 threads
        int id  = tid + i * NTHREADS;
        int row = id >> 5;
        int c   = (id & 31) * 4;
        int m   = m0 + row;
        if (m < cnt) {
            float4 v = *reinterpret_cast<const float4*>(&sC[row * LDC + c]);
            v.x = 0.5f * v.x * (1.0f + erff(v.x * 0.70710678118654752f));
            v.y = 0.5f * v.y * (1.0f + erff(v.y * 0.70710678118654752f));
            v.z = 0.5f * v.z * (1.0f + erff(v.z * 0.70710678118654752f));
            v.w = 0.5f * v.w * (1.0f + erff(v.w * 0.70710678118654752f));
            __half2 h0 = __floats2half2_rn(v.x, v.y);
            __half2 h1 = __floats2half2_rn(v.z, v.w);
            __half2* dst = reinterpret_cast<__half2*>(
                &g_act[(size_t)(e * CAP + m) * F_DIM + n0 + c]);
            dst[0] = h0;
            dst[1] = h1;
        }
    }
}

// ---------------- GEMM2: y = act_h @ w2h -------------------------------------
// grid: (H/BN=8, CAP/BM=16, E), block: 256
__global__ __launch_bounds__(NTHREADS, 2) void gemm2_kernel()
{
    extern __shared__ __align__(16) __half smem[];
    const int e   = blockIdx.z;
    const int cnt = g_cnt[e];
    const int m0  = blockIdx.y * BM;
    if (m0 >= cnt) return;
    const int n0  = blockIdx.x * BN;
    const int tid = threadIdx.x;
    const int w   = tid >> 5;
    const int warp_m = w >> 1;
    const int warp_n = w & 1;

    int a_row[4], a_col[4], b_row[4], b_col[4];
#pragma unroll
    for (int i = 0; i < 4; i++) {
        int id = tid + i * NTHREADS;
        a_row[i] = id >> 3;
        a_col[i] = (id & 7) * 8;
        b_row[i] = id >> 4;
        b_col[i] = (id & 15) * 8;
    }

    const __half* A   = &g_act[(size_t)(e * CAP) * F_DIM];  // stale rows>=cnt unread
    const __half* W2e = &g_w2h[(size_t)e * F_DIM * H_DIM];

    Frags fr;
#pragma unroll
    for (int i = 0; i < 2; i++)
#pragma unroll
        for (int j = 0; j < 4; j++) wmma::fill_fragment(fr.acc[i][j], 0.0f);

    const int NK = F_DIM / BKH;   // 64

    {
        __half* sA = smem;
        __half* sB = smem + BM * LDA;
#pragma unroll
        for (int i = 0; i < 4; i++)
            cp_async16(&sA[a_row[i] * LDA + a_col[i]],
                       &A[(size_t)(m0 + a_row[i]) * F_DIM + a_col[i]], true);
#pragma unroll
        for (int i = 0; i < 4; i++)
            cp_async16(&sB[b_row[i] * LDB + b_col[i]],
                       &W2e[(size_t)b_row[i] * H_DIM + n0 + b_col[i]], true);
        CP_COMMIT();
    }

    for (int kt = 0; kt < NK; kt++) {
        const int cur = kt & 1;
        if (kt + 1 < NK) {
            const int k0 = (kt + 1) * BKH;
            __half* sA = smem + (cur ^ 1) * STAGE_HALFS;
            __half* sB = sA + BM * LDA;
#pragma unroll
            for (int i = 0; i < 4; i++)
                cp_async16(&sA[a_row[i] * LDA + a_col[i]],
                           &A[(size_t)(m0 + a_row[i]) * F_DIM + k0 + a_col[i]], true);
#pragma unroll
            for (int i = 0; i < 4; i++)
                cp_async16(&sB[b_row[i] * LDB + b_col[i]],
                           &W2e[(size_t)(k0 + b_row[i]) * H_DIM + n0 + b_col[i]], true);
            CP_COMMIT();
            CP_WAIT(1);
        } else {
            CP_WAIT(0);
        }
        __syncthreads();
        mma_stage(smem + cur * STAGE_HALFS, smem + cur * STAGE_HALFS + BM * LDA,
                  warp_m, warp_n, fr);
        __syncthreads();
    }

    // epilogue: store accumulators straight to g_y (fp32)
#pragma unroll
    for (int i = 0; i < 2; i++)
#pragma unroll
        for (int j = 0; j < 4; j++)
            wmma::store_matrix_sync(
                &g_y[(size_t)(e * CAP + m0 + warp_m * 32 + i * 16) * H_DIM
                     + n0 + warp_n * 64 + j * 16],
                fr.acc[i][j], H_DIM, wmma::mem_row_major);
}

// ---------------- combine: out = residual + sum_e p * y ---------------------
__global__ void combine_kernel(const float* __restrict__ res,
                               const float* __restrict__ probs,
                               float* __restrict__ out)
{
    int t = blockIdx.x;
    int h = threadIdx.x * 4;
    float4 acc = *reinterpret_cast<const float4*>(&res[(size_t)t * H_DIM + h]);
#pragma unroll
    for (int e = 0; e < E_NUM; e++) {
        float p = probs[t * E_NUM + e];
        if (p > 0.0f) {
            int s = g_slot[t * E_NUM + e];
            float4 y = *reinterpret_cast<const float4*>(&g_y[(size_t)s * H_DIM + h]);
            acc.x += p * y.x;
            acc.y += p * y.y;
            acc.z += p * y.z;
            acc.w += p * y.w;
        }
    }
    *reinterpret_cast<float4*>(&out[(size_t)t * H_DIM + h]) = acc;
}

// ---------------- launcher ---------------------------------------------------
extern "C" void kernel_launch(void* const* d_in, const int* in_sizes, int n_in,
                              void* d_out, int out_size)
{
    const float* x     = (const float*)d_in[0];
    const float* res   = (const float*)d_in[1];
    const float* probs = (const float*)d_in[2];
    const float* w1    = (const float*)d_in[4];
    const float* w2    = (const float*)d_in[5];
    float* out = (float*)d_out;

    __half* xh;  cudaGetSymbolAddress((void**)&xh,  g_xh);
    __half* w1h; cudaGetSymbolAddress((void**)&w1h, g_w1h);
    __half* w2h; cudaGetSymbolAddress((void**)&w2h, g_w2h);

    (void)cudaFuncSetAttribute(gemm1_kernel,
                               cudaFuncAttributeMaxDynamicSharedMemorySize, SMEM_BYTES);
    (void)cudaFuncSetAttribute(gemm2_kernel,
                               cudaFuncAttributeMaxDynamicSharedMemorySize, SMEM_BYTES);

    zero_cnt_kernel<<<1, 32>>>();
    route_kernel<<<T_TOK / 256, 256>>>(probs);
    f2h_kernel<<<512, 256>>>(x,  xh,  (size_t)T_TOK * H_DIM / 4);
    f2h_kernel<<<2048, 256>>>(w1, w1h, (size_t)E_NUM * H_DIM * F_DIM / 4);
    f2h_kernel<<<2048, 256>>>(w2, w2h, (size_t)E_NUM * F_DIM * H_DIM / 4);
    gemm1_kernel<<<dim3(F_DIM / BN, CAP / BM, E_NUM), NTHREADS, SMEM_BYTES>>>();
    gemm2_kernel<<<dim3(H_DIM / BN, CAP / BM, E_NUM), NTHREADS, SMEM_BYTES>>>();
    combine_kernel<<<T_TOK, 256>>>(res, probs, out);
}

// round 8
// speedup vs baseline: 4.3881x; 1.0199x over previous
#include <cuda_runtime.h>
#include <cuda_fp16.h>
#include <mma.h>
#include <math.h>
#include <stdint.h>

using namespace nvcuda;

// Problem constants
#define T_TOK 2048
#define H_DIM 1024
#define F_DIM 4096
#define E_NUM 4
#define CAP   2048

// GEMM tiling: 128x128 tile, BK=64 halves, 3-stage cp.async pipeline
#define BM 128
#define BN 128
#define BKH 64          // K elements (half) per stage
#define LDA 72          // BKH + 8 pad (halves)
#define LDB 136         // BN + 8 pad (halves)
#define LDC 132         // floats, epilogue staging
#define NTHREADS 256
#define STAGES 3

#define STAGE_HALFS (BM * LDA + BKH * LDB)                      // 17920
#define SMEM_BYTES  (STAGES * STAGE_HALFS * (int)sizeof(__half)) // 107520

// ---------------- scratch (static device globals; no allocation) ------------
__device__ __half g_xh[(size_t)T_TOK * H_DIM];
__device__ __half g_w1h[(size_t)E_NUM * H_DIM * F_DIM];
__device__ __half g_w2h[(size_t)E_NUM * F_DIM * H_DIM];
__device__ __half g_act[(size_t)E_NUM * CAP * F_DIM];
__device__ float  g_y[(size_t)E_NUM * CAP * H_DIM];
__device__ int    g_cnt[E_NUM];
__device__ int    g_tok[E_NUM * CAP];
__device__ int    g_slot[T_TOK * E_NUM];

// ---------------- cp.async helpers ------------------------------------------
__device__ __forceinline__ void cp_async16(__half* smem_dst, const __half* gmem_src,
                                           bool pred) {
    unsigned int saddr = (unsigned int)__cvta_generic_to_shared(smem_dst);
    int sz = pred ? 16 : 0;   // src-size 0 -> zero-fill destination
    asm volatile("cp.async.cg.shared.global [%0], [%1], 16, %2;\n"
                 :: "r"(saddr), "l"(gmem_src), "r"(sz));
}
#define CP_COMMIT()  asm volatile("cp.async.commit_group;\n" ::)
#define CP_WAIT(n)   asm volatile("cp.async.wait_group %0;\n" :: "n"(n))

// ---------------- fp32 -> fp16 convert ---------------------------------------
__global__ void f2h_kernel(const float* __restrict__ src, __half* __restrict__ dst,
                           size_t n4) {   // n4 = n/4
    size_t i = (size_t)blockIdx.x * blockDim.x + threadIdx.x;
    size_t stride = (size_t)gridDim.x * blockDim.x;
    for (; i < n4; i += stride) {
        float4 v = reinterpret_cast<const float4*>(src)[i];
        __half2 h0 = __floats2half2_rn(v.x, v.y);
        __half2 h1 = __floats2half2_rn(v.z, v.w);
        reinterpret_cast<__half2*>(dst)[i * 2 + 0] = h0;
        reinterpret_cast<__half2*>(dst)[i * 2 + 1] = h1;
    }
}

// ---------------- routing compaction ----------------------------------------
__global__ void zero_cnt_kernel() {
    if (threadIdx.x < E_NUM) g_cnt[threadIdx.x] = 0;
}

__global__ void route_kernel(const float* __restrict__ probs) {
    int t = blockIdx.x * blockDim.x + threadIdx.x;
    if (t >= T_TOK) return;
#pragma unroll
    for (int e = 0; e < E_NUM; e++) {
        float p = probs[t * E_NUM + e];
        if (p > 0.0f) {
            int pos = atomicAdd(&g_cnt[e], 1);
            g_tok[e * CAP + pos] = t;
            g_slot[t * E_NUM + e] = e * CAP + pos;
        }
    }
}

// ---------------- shared MMA core -------------------------------------------
// 8 warps: warp_m = w>>1 (4 rows of 32), warp_n = w&1 (2 cols of 64)
struct Frags {
    wmma::fragment<wmma::accumulator, 16, 16, 16, float> acc[2][4];
};

__device__ __forceinline__ void mma_stage(const __half* sA, const __half* sB,
                                          int warp_m, int warp_n, Frags& fr) {
#pragma unroll
    for (int kk = 0; kk < BKH; kk += 16) {
        wmma::fragment<wmma::matrix_a, 16, 16, 16, __half, wmma::row_major> a[2];
        wmma::fragment<wmma::matrix_b, 16, 16, 16, __half, wmma::row_major> b[4];
#pragma unroll
        for (int i = 0; i < 2; i++)
            wmma::load_matrix_sync(a[i], &sA[(warp_m * 32 + i * 16) * LDA + kk], LDA);
#pragma unroll
        for (int j = 0; j < 4; j++)
            wmma::load_matrix_sync(b[j], &sB[kk * LDB + warp_n * 64 + j * 16], LDB);
#pragma unroll
        for (int i = 0; i < 2; i++)
#pragma unroll
            for (int j = 0; j < 4; j++)
                wmma::mma_sync(fr.acc[i][j], a[i], b[j], fr.acc[i][j]);
    }
}

// ---------------- GEMM1: act = gelu( gather(Xh) @ w1h ) ---------------------
// grid: (F/BN=32, CAP/BM=16, E), block: 256
__global__ __launch_bounds__(NTHREADS, 2) void gemm1_kernel()
{
    extern __shared__ __align__(16) __half smem[];
    const int e   = blockIdx.z;
    const int cnt = g_cnt[e];
    const int m0  = blockIdx.y * BM;
    if (m0 >= cnt) return;
    const int n0  = blockIdx.x * BN;
    const int tid = threadIdx.x;
    const int w   = tid >> 5;
    const int warp_m = w >> 1;
    const int warp_n = w & 1;

    // A tile: 128 rows x 64 halves = 8 chunks(16B)/row, 1024 chunks, 4/thread
    int a_row[4], a_col[4], a_tok[4];
    bool a_ok[4];
#pragma unroll
    for (int i = 0; i < 4; i++) {
        int id = tid + i * NTHREADS;
        a_row[i] = id >> 3;
        a_col[i] = (id & 7) * 8;          // half offset
        int m = m0 + a_row[i];
        a_ok[i] = (m < cnt);
        a_tok[i] = a_ok[i] ? __ldg(&g_tok[e * CAP + m]) : 0;
    }
    // B tile: 64 rows x 128 halves = 16 chunks/row, 1024 chunks, 4/thread
    int b_row[4], b_col[4];
#pragma unroll
    for (int i = 0; i < 4; i++) {
        int id = tid + i * NTHREADS;
        b_row[i] = id >> 4;
        b_col[i] = (id & 15) * 8;
    }

    const __half* W1e = &g_w1h[(size_t)e * H_DIM * F_DIM];

    Frags fr;
#pragma unroll
    for (int i = 0; i < 2; i++)
#pragma unroll
        for (int j = 0; j < 4; j++) wmma::fill_fragment(fr.acc[i][j], 0.0f);

    const int NK = H_DIM / BKH;   // 16

    // prologue: issue stages 0 and 1 (one commit-group each)
#pragma unroll
    for (int s = 0; s < STAGES - 1; s++) {
        __half* sA = smem + s * STAGE_HALFS;
        __half* sB = sA + BM * LDA;
        const int k0 = s * BKH;
#pragma unroll
        for (int i = 0; i < 4; i++)
            cp_async16(&sA[a_row[i] * LDA + a_col[i]],
                       &g_xh[(size_t)a_tok[i] * H_DIM + k0 + a_col[i]], a_ok[i]);
#pragma unroll
        for (int i = 0; i < 4; i++)
            cp_async16(&sB[b_row[i] * LDB + b_col[i]],
                       &W1e[(size_t)(k0 + b_row[i]) * F_DIM + n0 + b_col[i]], true);
        CP_COMMIT();
    }

    int buf = 0;           // buffer holding stage kt
    int nbuf = STAGES - 1; // buffer to fill with stage kt+2
    for (int kt = 0; kt < NK; kt++) {
        CP_WAIT(1);            // stage kt complete (only kt+1's group may remain)
        __syncthreads();       // writes visible; prior readers of nbuf are done
        if (kt + 2 < NK) {
            __half* sA = smem + nbuf * STAGE_HALFS;
            __half* sB = sA + BM * LDA;
            const int k0 = (kt + 2) * BKH;
#pragma unroll
            for (int i = 0; i < 4; i++)
                cp_async16(&sA[a_row[i] * LDA + a_col[i]],
                           &g_xh[(size_t)a_tok[i] * H_DIM + k0 + a_col[i]], a_ok[i]);
#pragma unroll
            for (int i = 0; i < 4; i++)
                cp_async16(&sB[b_row[i] * LDB + b_col[i]],
                           &W1e[(size_t)(k0 + b_row[i]) * F_DIM + n0 + b_col[i]], true);
        }
        CP_COMMIT();           // unconditional: keeps group count aligned
        mma_stage(smem + buf * STAGE_HALFS,
                  smem + buf * STAGE_HALFS + BM * LDA, warp_m, warp_n, fr);
        buf  = (buf  == STAGES - 1) ? 0 : buf + 1;
        nbuf = (nbuf == STAGES - 1) ? 0 : nbuf + 1;
    }
    CP_WAIT(0);
    __syncthreads();

    // epilogue: stage C (float) in smem, gelu, convert to half, store
    float* sC = reinterpret_cast<float*>(smem);
#pragma unroll
    for (int i = 0; i < 2; i++)
#pragma unroll
        for (int j = 0; j < 4; j++)
            wmma::store_matrix_sync(
                &sC[(warp_m * 32 + i * 16) * LDC + warp_n * 64 + j * 16],
                fr.acc[i][j], LDC, wmma::mem_row_major);
    __syncthreads();
#pragma unroll
    for (int i = 0; i < 16; i++) {       // 4096 4-elem groups / 256 threads
        int id  = tid + i * NTHREADS;
        int row = id >> 5;
        int c   = (id & 31) * 4;
        int m   = m0 + row;
        if (m < cnt) {
            float4 v = *reinterpret_cast<const float4*>(&sC[row * LDC + c]);
            v.x = 0.5f * v.x * (1.0f + erff(v.x * 0.70710678118654752f));
            v.y = 0.5f * v.y * (1.0f + erff(v.y * 0.70710678118654752f));
            v.z = 0.5f * v.z * (1.0f + erff(v.z * 0.70710678118654752f));
            v.w = 0.5f * v.w * (1.0f + erff(v.w * 0.70710678118654752f));
            __half2 h0 = __floats2half2_rn(v.x, v.y);
            __half2 h1 = __floats2half2_rn(v.z, v.w);
            __half2* dst = reinterpret_cast<__half2*>(
                &g_act[(size_t)(e * CAP + m) * F_DIM + n0 + c]);
            dst[0] = h0;
            dst[1] = h1;
        }
    }
}

// ---------------- GEMM2: y = act_h @ w2h -------------------------------------
// grid: (H/BN=8, CAP/BM=16, E), block: 256
__global__ __launch_bounds__(NTHREADS, 2) void gemm2_kernel()
{
    extern __shared__ __align__(16) __half smem[];
    const int e   = blockIdx.z;
    const int cnt = g_cnt[e];
    const int m0  = blockIdx.y * BM;
    if (m0 >= cnt) return;
    const int n0  = blockIdx.x * BN;
    const int tid = threadIdx.x;
    const int w   = tid >> 5;
    const int warp_m = w >> 1;
    const int warp_n = w & 1;

    int a_row[4], a_col[4], b_row[4], b_col[4];
#pragma unroll
    for (int i = 0; i < 4; i++) {
        int id = tid + i * NTHREADS;
        a_row[i] = id >> 3;
        a_col[i] = (id & 7) * 8;
        b_row[i] = id >> 4;
        b_col[i] = (id & 15) * 8;
    }

    const __half* A   = &g_act[(size_t)(e * CAP) * F_DIM];  // stale rows>=cnt unread
    const __half* W2e = &g_w2h[(size_t)e * F_DIM * H_DIM];

    Frags fr;
#pragma unroll
    for (int i = 0; i < 2; i++)
#pragma unroll
        for (int j = 0; j < 4; j++) wmma::fill_fragment(fr.acc[i][j], 0.0f);

    const int NK = F_DIM / BKH;   // 64

#pragma unroll
    for (int s = 0; s < STAGES - 1; s++) {
        __half* sA = smem + s * STAGE_HALFS;
        __half* sB = sA + BM * LDA;
        const int k0 = s * BKH;
#pragma unroll
        for (int i = 0; i < 4; i++)
            cp_async16(&sA[a_row[i] * LDA + a_col[i]],
                       &A[(size_t)(m0 + a_row[i]) * F_DIM + k0 + a_col[i]], true);
#pragma unroll
        for (int i = 0; i < 4; i++)
            cp_async16(&sB[b_row[i] * LDB + b_col[i]],
                       &W2e[(size_t)(k0 + b_row[i]) * H_DIM + n0 + b_col[i]], true);
        CP_COMMIT();
    }

    int buf = 0, nbuf = STAGES - 1;
    for (int kt = 0; kt < NK; kt++) {
        CP_WAIT(1);
        __syncthreads();
        if (kt + 2 < NK) {
            __half* sA = smem + nbuf * STAGE_HALFS;
            __half* sB = sA + BM * LDA;
            const int k0 = (kt + 2) * BKH;
#pragma unroll
            for (int i = 0; i < 4; i++)
                cp_async16(&sA[a_row[i] * LDA + a_col[i]],
                           &A[(size_t)(m0 + a_row[i]) * F_DIM + k0 + a_col[i]], true);
#pragma unroll
            for (int i = 0; i < 4; i++)
                cp_async16(&sB[b_row[i] * LDB + b_col[i]],
                           &W2e[(size_t)(k0 + b_row[i]) * H_DIM + n0 + b_col[i]], true);
        }
        CP_COMMIT();
        mma_stage(smem + buf * STAGE_HALFS,
                  smem + buf * STAGE_HALFS + BM * LDA, warp_m, warp_n, fr);
        buf  = (buf  == STAGES - 1) ? 0 : buf + 1;
        nbuf = (nbuf == STAGES - 1) ? 0 : nbuf + 1;
    }
    CP_WAIT(0);

    // epilogue: store accumulators straight to g_y (fp32)
#pragma unroll
    for (int i = 0; i < 2; i++)
#pragma unroll
        for (int j = 0; j < 4; j++)
            wmma::store_matrix_sync(
                &g_y[(size_t)(e * CAP + m0 + warp_m * 32 + i * 16) * H_DIM
                     + n0 + warp_n * 64 + j * 16],
                fr.acc[i][j], H_DIM, wmma::mem_row_major);
}

// ---------------- combine: out = residual + sum_e p * y ---------------------
__global__ void combine_kernel(const float* __restrict__ res,
                               const float* __restrict__ probs,
                               float* __restrict__ out)
{
    int t = blockIdx.x;
    int h = threadIdx.x * 4;
    float4 acc = *reinterpret_cast<const float4*>(&res[(size_t)t * H_DIM + h]);
#pragma unroll
    for (int e = 0; e < E_NUM; e++) {
        float p = probs[t * E_NUM + e];
        if (p > 0.0f) {
            int s = g_slot[t * E_NUM + e];
            float4 y = *reinterpret_cast<const float4*>(&g_y[(size_t)s * H_DIM + h]);
            acc.x += p * y.x;
            acc.y += p * y.y;
            acc.z += p * y.z;
            acc.w += p * y.w;
        }
    }
    *reinterpret_cast<float4*>(&out[(size_t)t * H_DIM + h]) = acc;
}

// ---------------- launcher ---------------------------------------------------
extern "C" void kernel_launch(void* const* d_in, const int* in_sizes, int n_in,
                              void* d_out, int out_size)
{
    const float* x     = (const float*)d_in[0];
    const float* res   = (const float*)d_in[1];
    const float* probs = (const float*)d_in[2];
    const float* w1    = (const float*)d_in[4];
    const float* w2    = (const float*)d_in[5];
    float* out = (float*)d_out;

    __half* xh;  cudaGetSymbolAddress((void**)&xh,  g_xh);
    __half* w1h; cudaGetSymbolAddress((void**)&w1h, g_w1h);
    __half* w2h; cudaGetSymbolAddress((void**)&w2h, g_w2h);

    (void)cudaFuncSetAttribute(gemm1_kernel,
                               cudaFuncAttributeMaxDynamicSharedMemorySize, SMEM_BYTES);
    (void)cudaFuncSetAttribute(gemm2_kernel,
                               cudaFuncAttributeMaxDynamicSharedMemorySize, SMEM_BYTES);

    zero_cnt_kernel<<<1, 32>>>();
    route_kernel<<<T_TOK / 256, 256>>>(probs);
    f2h_kernel<<<512, 256>>>(x,  xh,  (size_t)T_TOK * H_DIM / 4);
    f2h_kernel<<<2048, 256>>>(w1, w1h, (size_t)E_NUM * H_DIM * F_DIM / 4);
    f2h_kernel<<<2048, 256>>>(w2, w2h, (size_t)E_NUM * F_DIM * H_DIM / 4);
    gemm1_kernel<<<dim3(F_DIM / BN, CAP / BM, E_NUM), NTHREADS, SMEM_BYTES>>>();
    gemm2_kernel<<<dim3(H_DIM / BN, CAP / BM, E_NUM), NTHREADS, SMEM_BYTES>>>();
    combine_kernel<<<T_TOK, 256>>>(res, probs, out);
}

// round 9
// speedup vs baseline: 4.4480x; 1.0136x over previous
#include <cuda_runtime.h>
#include <cuda_fp16.h>
#include <mma.h>
#include <math.h>
#include <stdint.h>

using namespace nvcuda;

// Problem constants
#define T_TOK 2048
#define H_DIM 1024
#define F_DIM 4096
#define E_NUM 4
#define CAP   2048

// GEMM tiling: 128x128 tile, BK=32 halves, 2-stage smem + reg-staged fp32 B
#define BM 128
#define BN 128
#define BKH 32          // K elements per stage
#define LDA 40          // BKH + 8 pad (halves)
#define LDB 136         // BN + 8 pad (halves)
#define LDC 132         // floats, epilogue staging
#define NTHREADS 256

#define A_HALFS (BM * LDA)                 // 5120
#define STAGE_HALFS (BM * LDA + BKH * LDB) // 9472
#define SMEM_BYTES 67584                   // max(2*STAGE_HALFS*2, 128*132*4)

// ---------------- scratch (static device globals; no allocation) ------------
__device__ __half g_xh[(size_t)T_TOK * H_DIM];
__device__ __half g_act[(size_t)E_NUM * CAP * F_DIM];
__device__ float  g_y[(size_t)E_NUM * CAP * H_DIM];
__device__ int    g_cnt[E_NUM];
__device__ int    g_tok[E_NUM * CAP];
__device__ int    g_slot[T_TOK * E_NUM];

// ---------------- cp.async helpers ------------------------------------------
__device__ __forceinline__ void cp_async16(__half* smem_dst, const __half* gmem_src,
                                           bool pred) {
    unsigned int saddr = (unsigned int)__cvta_generic_to_shared(smem_dst);
    int sz = pred ? 16 : 0;   // src-size 0 -> zero-fill destination
    asm volatile("cp.async.cg.shared.global [%0], [%1], 16, %2;\n"
                 :: "r"(saddr), "l"(gmem_src), "r"(sz));
}
#define CP_COMMIT()  asm volatile("cp.async.commit_group;\n" ::)
#define CP_WAIT0()   asm volatile("cp.async.wait_group 0;\n" ::)

// ---------------- fp32 -> fp16 convert (x only) ------------------------------
__global__ void f2h_kernel(const float* __restrict__ src, __half* __restrict__ dst,
                           size_t n4) {
    size_t i = (size_t)blockIdx.x * blockDim.x + threadIdx.x;
    size_t stride = (size_t)gridDim.x * blockDim.x;
    for (; i < n4; i += stride) {
        float4 v = reinterpret_cast<const float4*>(src)[i];
        reinterpret_cast<__half2*>(dst)[i * 2 + 0] = __floats2half2_rn(v.x, v.y);
        reinterpret_cast<__half2*>(dst)[i * 2 + 1] = __floats2half2_rn(v.z, v.w);
    }
}

// ---------------- routing compaction ----------------------------------------
__global__ void zero_cnt_kernel() {
    if (threadIdx.x < E_NUM) g_cnt[threadIdx.x] = 0;
}

__global__ void route_kernel(const float* __restrict__ probs) {
    int t = blockIdx.x * blockDim.x + threadIdx.x;
    if (t >= T_TOK) return;
#pragma unroll
    for (int e = 0; e < E_NUM; e++) {
        float p = probs[t * E_NUM + e];
        if (p > 0.0f) {
            int pos = atomicAdd(&g_cnt[e], 1);
            g_tok[e * CAP + pos] = t;
            g_slot[t * E_NUM + e] = e * CAP + pos;
        }
    }
}

// ---------------- shared MMA core -------------------------------------------
// 8 warps: warp_m = w>>1 (4 rows of 32), warp_n = w&1 (2 cols of 64)
struct Frags {
    wmma::fragment<wmma::accumulator, 16, 16, 16, float> acc[2][4];
};

__device__ __forceinline__ void mma_stage(const __half* sA, const __half* sB,
                                          int warp_m, int warp_n, Frags& fr) {
#pragma unroll
    for (int kk = 0; kk < BKH; kk += 16) {
        wmma::fragment<wmma::matrix_a, 16, 16, 16, __half, wmma::row_major> a[2];
        wmma::fragment<wmma::matrix_b, 16, 16, 16, __half, wmma::row_major> b[4];
#pragma unroll
        for (int i = 0; i < 2; i++)
            wmma::load_matrix_sync(a[i], &sA[(warp_m * 32 + i * 16) * LDA + kk], LDA);
#pragma unroll
        for (int j = 0; j < 4; j++)
            wmma::load_matrix_sync(b[j], &sB[kk * LDB + warp_n * 64 + j * 16], LDB);
#pragma unroll
        for (int i = 0; i < 2; i++)
#pragma unroll
            for (int j = 0; j < 4; j++)
                wmma::mma_sync(fr.acc[i][j], a[i], b[j], fr.acc[i][j]);
    }
}

// ---------------- B loader: fp32 gmem -> regs -> cvt -> smem half ------------
// B tile: BKH x BN floats = 32x128 = 1024 float4 chunks, 4 per thread
__device__ __forceinline__ void ldg_b(float4* r, const float* __restrict__ W,
                                      int ldw, int n0, int k0, int tid) {
#pragma unroll
    for (int i = 0; i < 4; i++) {
        int id  = tid + i * NTHREADS;
        int row = id >> 5;
        int c4  = (id & 31) * 4;
        r[i] = *reinterpret_cast<const float4*>(&W[(size_t)(k0 + row) * ldw + n0 + c4]);
    }
}
__device__ __forceinline__ void sts_b(__half* sB, const float4* r, int tid) {
#pragma unroll
    for (int i = 0; i < 4; i++) {
        int id  = tid + i * NTHREADS;
        int row = id >> 5;
        int c4  = (id & 31) * 4;
        __half2* d = reinterpret_cast<__half2*>(&sB[row * LDB + c4]);
        d[0] = __floats2half2_rn(r[i].x, r[i].y);
        d[1] = __floats2half2_rn(r[i].z, r[i].w);
    }
}

// ---------------- GEMM1: act = gelu( gather(Xh) @ w1 ) ----------------------
// grid: (F/BN=32, CAP/BM=16, E), block: 256
__global__ __launch_bounds__(NTHREADS, 2) void gemm1_kernel(
    const float* __restrict__ W1)
{
    extern __shared__ __align__(16) __half smem[];
    const int e   = blockIdx.z;
    const int cnt = g_cnt[e];
    const int m0  = blockIdx.y * BM;
    if (m0 >= cnt) return;
    const int n0  = blockIdx.x * BN;
    const int tid = threadIdx.x;
    const int w   = tid >> 5;
    const int warp_m = w >> 1;
    const int warp_n = w & 1;

    // A tile: 128 rows x 32 halves = 4 chunks(16B)/row, 512 chunks, 2/thread
    int a_row[2], a_col[2], a_tok[2];
    bool a_ok[2];
#pragma unroll
    for (int i = 0; i < 2; i++) {
        int id = tid + i * NTHREADS;
        a_row[i] = id >> 2;
        a_col[i] = (id & 3) * 8;          // half offset
        int m = m0 + a_row[i];
        a_ok[i] = (m < cnt);
        a_tok[i] = a_ok[i] ? __ldg(&g_tok[e * CAP + m]) : 0;
    }
    const float* W1e = &W1[(size_t)e * H_DIM * F_DIM];

    Frags fr;
#pragma unroll
    for (int i = 0; i < 2; i++)
#pragma unroll
        for (int j = 0; j < 4; j++) wmma::fill_fragment(fr.acc[i][j], 0.0f);

    const int NK = H_DIM / BKH;   // 32
    float4 regsB[4];

    // prologue
    {
        __half* sA0 = smem;
        __half* sB0 = smem + A_HALFS;
        ldg_b(regsB, W1e, F_DIM, n0, 0, tid);
        sts_b(sB0, regsB, tid);
#pragma unroll
        for (int i = 0; i < 2; i++)
            cp_async16(&sA0[a_row[i] * LDA + a_col[i]],
                       &g_xh[(size_t)a_tok[i] * H_DIM + a_col[i]], a_ok[i]);
        CP_COMMIT();
        __half* sA1 = smem + STAGE_HALFS;
#pragma unroll
        for (int i = 0; i < 2; i++)
            cp_async16(&sA1[a_row[i] * LDA + a_col[i]],
                       &g_xh[(size_t)a_tok[i] * H_DIM + BKH + a_col[i]], a_ok[i]);
        CP_COMMIT();
        ldg_b(regsB, W1e, F_DIM, n0, BKH, tid);
        asm volatile("cp.async.wait_group 1;\n" ::);
        __syncthreads();
    }

#pragma unroll 1
    for (int kt = 0; kt < NK; kt++) {
        __half* cur   = smem + (kt & 1) * STAGE_HALFS;
        __half* other = smem + ((kt & 1) ^ 1) * STAGE_HALFS;
        if (kt + 1 < NK) sts_b(other + A_HALFS, regsB, tid);      // B[kt+1]
        if (kt + 2 < NK) ldg_b(regsB, W1e, F_DIM, n0, (kt + 2) * BKH, tid);
        mma_stage(cur, cur + A_HALFS, warp_m, warp_n, fr);
        CP_WAIT0();           // drain A[kt+1] (only group in flight)
        __syncthreads();
        if (kt + 2 < NK) {
            const int k0 = (kt + 2) * BKH;
#pragma unroll
            for (int i = 0; i < 2; i++)
                cp_async16(&cur[a_row[i] * LDA + a_col[i]],
                           &g_xh[(size_t)a_tok[i] * H_DIM + k0 + a_col[i]], a_ok[i]);
            CP_COMMIT();
        }
    }

    // epilogue: stage C (float) in smem, gelu, convert to half, store
    float* sC = reinterpret_cast<float*>(smem);
#pragma unroll
    for (int i = 0; i < 2; i++)
#pragma unroll
        for (int j = 0; j < 4; j++)
            wmma::store_matrix_sync(
                &sC[(warp_m * 32 + i * 16) * LDC + warp_n * 64 + j * 16],
                fr.acc[i][j], LDC, wmma::mem_row_major);
    __syncthreads();
#pragma unroll
    for (int i = 0; i < 16; i++) {       // 4096 4-elem groups / 256 threads
        int id  = tid + i * NTHREADS;
        int row = id >> 5;
        int c   = (id & 31) * 4;
        int m   = m0 + row;
        if (m < cnt) {
            float4 v = *reinterpret_cast<const float4*>(&sC[row * LDC + c]);
            v.x = 0.5f * v.x * (1.0f + erff(v.x * 0.70710678118654752f));
            v.y = 0.5f * v.y * (1.0f + erff(v.y * 0.70710678118654752f));
            v.z = 0.5f * v.z * (1.0f + erff(v.z * 0.70710678118654752f));
            v.w = 0.5f * v.w * (1.0f + erff(v.w * 0.70710678118654752f));
            __half2* dst = reinterpret_cast<__half2*>(
                &g_act[(size_t)(e * CAP + m) * F_DIM + n0 + c]);
            dst[0] = __floats2half2_rn(v.x, v.y);
            dst[1] = __floats2half2_rn(v.z, v.w);
        }
    }
}

// ---------------- GEMM2: y = act_h @ w2 --------------------------------------
// grid: (H/BN=8, CAP/BM=16, E), block: 256
__global__ __launch_bounds__(NTHREADS, 2) void gemm2_kernel(
    const float* __restrict__ W2)
{
    extern __shared__ __align__(16) __half smem[];
    const int e   = blockIdx.z;
    const int cnt = g_cnt[e];
    const int m0  = blockIdx.y * BM;
    if (m0 >= cnt) return;
    const int n0  = blockIdx.x * BN;
    const int tid = threadIdx.x;
    const int w   = tid >> 5;
    const int warp_m = w >> 1;
    const int warp_n = w & 1;

    int a_row[2], a_col[2];
#pragma unroll
    for (int i = 0; i < 2; i++) {
        int id = tid + i * NTHREADS;
        a_row[i] = id >> 2;
        a_col[i] = (id & 3) * 8;
    }
    const __half* A   = &g_act[(size_t)(e * CAP) * F_DIM];  // stale rows>=cnt unread
    const float* W2e  = &W2[(size_t)e * F_DIM * H_DIM];

    Frags fr;
#pragma unroll
    for (int i = 0; i < 2; i++)
#pragma unroll
        for (int j = 0; j < 4; j++) wmma::fill_fragment(fr.acc[i][j], 0.0f);

    const int NK = F_DIM / BKH;   // 128
    float4 regsB[4];

    {
        __half* sA0 = smem;
        __half* sB0 = smem + A_HALFS;
        ldg_b(regsB, W2e, H_DIM, n0, 0, tid);
        sts_b(sB0, regsB, tid);
#pragma unroll
        for (int i = 0; i < 2; i++)
            cp_async16(&sA0[a_row[i] * LDA + a_col[i]],
                       &A[(size_t)(m0 + a_row[i]) * F_DIM + a_col[i]], true);
        CP_COMMIT();
        __half* sA1 = smem + STAGE_HALFS;
#pragma unroll
        for (int i = 0; i < 2; i++)
            cp_async16(&sA1[a_row[i] * LDA + a_col[i]],
                       &A[(size_t)(m0 + a_row[i]) * F_DIM + BKH + a_col[i]], true);
        CP_COMMIT();
        ldg_b(regsB, W2e, H_DIM, n0, BKH, tid);
        asm volatile("cp.async.wait_group 1;\n" ::);
        __syncthreads();
    }

#pragma unroll 1
    for (int kt = 0; kt < NK; kt++) {
        __half* cur   = smem + (kt & 1) * STAGE_HALFS;
        __half* other = smem + ((kt & 1) ^ 1) * STAGE_HALFS;
        if (kt + 1 < NK) sts_b(other + A_HALFS, regsB, tid);
        if (kt + 2 < NK) ldg_b(regsB, W2e, H_DIM, n0, (kt + 2) * BKH, tid);
        mma_stage(cur, cur + A_HALFS, warp_m, warp_n, fr);
        CP_WAIT0();
        __syncthreads();
        if (kt + 2 < NK) {
            const int k0 = (kt + 2) * BKH;
#pragma unroll
            for (int i = 0; i < 2; i++)
                cp_async16(&cur[a_row[i] * LDA + a_col[i]],
                           &A[(size_t)(m0 + a_row[i]) * F_DIM + k0 + a_col[i]], true);
            CP_COMMIT();
        }
    }

    // epilogue: store accumulators straight to g_y (fp32)
#pragma unroll
    for (int i = 0; i < 2; i++)
#pragma unroll
        for (int j = 0; j < 4; j++)
            wmma::store_matrix_sync(
                &g_y[(size_t)(e * CAP + m0 + warp_m * 32 + i * 16) * H_DIM
                     + n0 + warp_n * 64 + j * 16],
                fr.acc[i][j], H_DIM, wmma::mem_row_major);
}

// ---------------- combine: out = residual + sum_e p * y ---------------------
__global__ void combine_kernel(const float* __restrict__ res,
                               const float* __restrict__ probs,
                               float* __restrict__ out)
{
    int t = blockIdx.x;
    int h = threadIdx.x * 4;
    float4 acc = *reinterpret_cast<const float4*>(&res[(size_t)t * H_DIM + h]);
#pragma unroll
    for (int e = 0; e < E_NUM; e++) {
        float p = probs[t * E_NUM + e];
        if (p > 0.0f) {
            int s = g_slot[t * E_NUM + e];
            float4 y = *reinterpret_cast<const float4*>(&g_y[(size_t)s * H_DIM + h]);
            acc.x += p * y.x;
            acc.y += p * y.y;
            acc.z += p * y.z;
            acc.w += p * y.w;
        }
    }
    *reinterpret_cast<float4*>(&out[(size_t)t * H_DIM + h]) = acc;
}

// ---------------- launcher ---------------------------------------------------
extern "C" void kernel_launch(void* const* d_in, const int* in_sizes, int n_in,
                              void* d_out, int out_size)
{
    const float* x     = (const float*)d_in[0];
    const float* res   = (const float*)d_in[1];
    const float* probs = (const float*)d_in[2];
    const float* w1    = (const float*)d_in[4];
    const float* w2    = (const float*)d_in[5];
    float* out = (float*)d_out;

    __half* xh; cudaGetSymbolAddress((void**)&xh, g_xh);

    (void)cudaFuncSetAttribute(gemm1_kernel,
                               cudaFuncAttributeMaxDynamicSharedMemorySize, SMEM_BYTES);
    (void)cudaFuncSetAttribute(gemm2_kernel,
                               cudaFuncAttributeMaxDynamicSharedMemorySize, SMEM_BYTES);

    zero_cnt_kernel<<<1, 32>>>();
    route_kernel<<<T_TOK / 256, 256>>>(probs);
    f2h_kernel<<<512, 256>>>(x, xh, (size_t)T_TOK * H_DIM / 4);
    gemm1_kernel<<<dim3(F_DIM / BN, CAP / BM, E_NUM), NTHREADS, SMEM_BYTES>>>(w1);
    gemm2_kernel<<<dim3(H_DIM / BN, CAP / BM, E_NUM), NTHREADS, SMEM_BYTES>>>(w2);
    combine_kernel<<<T_TOK, 256>>>(res, probs, out);
}